// round 2
// baseline (speedup 1.0000x reference)
#include <cuda_runtime.h>
#include <cuda_bf16.h>

// Problem constants (fixed shapes from reference setup_inputs)
#define B_BATCH 8192
#define N_SUP   64
#define D_DIM   256
#define EPS     1e-8f

// Scratch for per-batch distances (allocation-free: __device__ global)
__device__ float g_dist[B_BATCH];

// Kernel 1: one CTA per batch row. 256 threads.
// Computes dist[b] = || query[b] - prototype[b] ||_2 (with +EPS under sqrt)
__global__ __launch_bounds__(256) void proto_dist_kernel(
    const float* __restrict__ query,     // (B, D)
    const float* __restrict__ support,   // (B, N, D)
    const int*   __restrict__ labels)    // (B, N)
{
    const int b   = blockIdx.x;
    const int tid = threadIdx.x;

    // 16B alignment required: s_part is written via float4 (STS.128)
    __shared__ __align__(16) float s_part[4][D_DIM];  // per-group partial proto sums
    __shared__ int s_lab[N_SUP];
    __shared__ int s_pos[N_SUP];
    __shared__ int s_cnt;
    __shared__ float s_red[8];           // warp partials for final reduce

    // Load labels for this batch row into shared
    if (tid < N_SUP) s_lab[tid] = labels[(size_t)b * N_SUP + tid];
    __syncthreads();

    // Deterministic compaction of positive indices (thread 0, serial —
    // ~64 LDS, negligible vs the ~32KB of HBM traffic per CTA)
    if (tid == 0) {
        int c = 0;
        #pragma unroll
        for (int n = 0; n < N_SUP; n++) {
            if (s_lab[n] == 1) s_pos[c++] = n;
        }
        s_cnt = c;
    }
    __syncthreads();

    const int cnt = s_cnt;

    // float4 accumulation: group g (tid>>6) walks rows i = g, g+4, ...
    // lane d4 (tid&63) owns dims [4*d4, 4*d4+4). Each row read = 64 lanes
    // * 16B = 1024B fully coalesced; negative rows are never touched.
    const int g  = tid >> 6;
    const int d4 = tid & 63;
    const float4* sup4 = reinterpret_cast<const float4*>(
        support + (size_t)b * N_SUP * D_DIM);

    float4 acc = make_float4(0.f, 0.f, 0.f, 0.f);
    for (int i = g; i < cnt; i += 4) {
        const int n = s_pos[i];
        float4 v = sup4[n * (D_DIM / 4) + d4];
        acc.x += v.x; acc.y += v.y; acc.z += v.z; acc.w += v.w;
    }
    // stash group partials (16B-aligned shared stores)
    reinterpret_cast<float4*>(s_part[g])[d4] = acc;
    __syncthreads();

    // Per-dim prototype for d = tid
    float p = s_part[0][tid] + s_part[1][tid] + s_part[2][tid] + s_part[3][tid];
    float proto;
    if (cnt > 0) {
        proto = p / (float)cnt;
    } else {
        // fallback: support_embs[b, 0, :]
        proto = support[(size_t)b * N_SUP * D_DIM + tid];
    }

    const float q = query[(size_t)b * D_DIM + tid];
    const float diff = q - proto;
    float v = diff * diff;

    // block reduce 256 -> 1
    #pragma unroll
    for (int off = 16; off > 0; off >>= 1)
        v += __shfl_xor_sync(0xFFFFFFFFu, v, off);
    if ((tid & 31) == 0) s_red[tid >> 5] = v;
    __syncthreads();
    if (tid < 8) {
        float w = s_red[tid];
        #pragma unroll
        for (int off = 4; off > 0; off >>= 1)
            w += __shfl_xor_sync(0xFFu, w, off);
        if (tid == 0) g_dist[b] = sqrtf(w + EPS);
    }
}

// Kernel 2: deterministic reduce of 8192 distances -> mean into d_out[0]
__global__ __launch_bounds__(256) void mean_reduce_kernel(float* __restrict__ out)
{
    const int tid = threadIdx.x;
    __shared__ float s_red[8];

    float v = 0.f;
    #pragma unroll
    for (int i = 0; i < B_BATCH / 256; i++)
        v += g_dist[tid + i * 256];

    #pragma unroll
    for (int off = 16; off > 0; off >>= 1)
        v += __shfl_xor_sync(0xFFFFFFFFu, v, off);
    if ((tid & 31) == 0) s_red[tid >> 5] = v;
    __syncthreads();
    if (tid < 8) {
        float w = s_red[tid];
        #pragma unroll
        for (int off = 4; off > 0; off >>= 1)
            w += __shfl_xor_sync(0xFFu, w, off);
        if (tid == 0) out[0] = w * (1.0f / (float)B_BATCH);
    }
}

extern "C" void kernel_launch(void* const* d_in, const int* in_sizes, int n_in,
                              void* d_out, int out_size)
{
    const float* query   = (const float*)d_in[0];
    const float* support = (const float*)d_in[1];
    const int*   labels  = (const int*)d_in[2];
    float* out = (float*)d_out;

    proto_dist_kernel<<<B_BATCH, 256>>>(query, support, labels);
    mean_reduce_kernel<<<1, 256>>>(out);
}

// round 3
// speedup vs baseline: 1.2834x; 1.2834x over previous
#include <cuda_runtime.h>
#include <cuda_bf16.h>

#define B_BATCH 8192
#define N_SUP   64
#define D_DIM   256
#define EPS     1e-8f

__device__ float g_dist[B_BATCH];
__device__ unsigned int g_counter = 0;

// One CTA per batch row, 256 threads. Last CTA to finish also does the mean.
__global__ __launch_bounds__(256) void proto_loss_kernel(
    const float* __restrict__ query,     // (B, D)
    const float* __restrict__ support,   // (B, N, D)
    const int*   __restrict__ labels,    // (B, N)
    float* __restrict__ out)             // scalar
{
    const int b   = blockIdx.x;
    const int tid = threadIdx.x;

    __shared__ __align__(16) float s_part[4][D_DIM];
    __shared__ int   s_lab[N_SUP];
    __shared__ int   s_cnt;
    __shared__ float s_red[8];
    __shared__ int   s_last;

    if (tid < N_SUP) s_lab[tid] = labels[(size_t)b * N_SUP + tid];
    __syncthreads();

    // thread 0 counts positives (overlaps with the load loop below; consumed
    // only after the next __syncthreads)
    if (tid == 0) {
        int c = 0;
        #pragma unroll
        for (int n = 0; n < N_SUP; n++) c += (s_lab[n] == 1);
        s_cnt = c;
    }

    // Predicated, fully-unrolled accumulation.
    // Group g (tid>>6, 2 warps) owns rows n = g, g+4, ..., g+60 (16 rows).
    // Lane d4 (tid&63) owns dims [4*d4, 4*d4+4). Row read = 64 lanes * 16B
    // = 1024B fully coalesced; label==0 rows issue no memory transaction.
    // Compile-time trip count -> ptxas batches predicated LDG.128 -> high MLP.
    const int g  = tid >> 6;
    const int d4 = tid & 63;
    const float4* __restrict__ sup4 = reinterpret_cast<const float4*>(
        support + (size_t)b * N_SUP * D_DIM);

    float4 acc = make_float4(0.f, 0.f, 0.f, 0.f);
    #pragma unroll
    for (int r = 0; r < 16; r++) {
        const int n = g + 4 * r;
        if (s_lab[n] == 1) {
            float4 v = sup4[n * (D_DIM / 4) + d4];
            acc.x += v.x; acc.y += v.y; acc.z += v.z; acc.w += v.w;
        }
    }
    reinterpret_cast<float4*>(s_part[g])[d4] = acc;
    __syncthreads();

    // Per-dim prototype for d = tid, with fallback to support[b,0,:]
    const int cnt = s_cnt;
    float p = s_part[0][tid] + s_part[1][tid] + s_part[2][tid] + s_part[3][tid];
    float proto = (cnt > 0) ? (p / (float)cnt)
                            : support[(size_t)b * N_SUP * D_DIM + tid];

    const float q = query[(size_t)b * D_DIM + tid];
    const float diff = q - proto;
    float v = diff * diff;

    #pragma unroll
    for (int off = 16; off > 0; off >>= 1)
        v += __shfl_xor_sync(0xFFFFFFFFu, v, off);
    if ((tid & 31) == 0) s_red[tid >> 5] = v;
    __syncthreads();
    if (tid < 8) {
        float w = s_red[tid];
        #pragma unroll
        for (int off = 4; off > 0; off >>= 1)
            w += __shfl_xor_sync(0xFFu, w, off);
        if (tid == 0) g_dist[b] = sqrtf(w + EPS);
    }

    // ---- last-block mean reduce (deterministic fixed-order sum) ----
    __threadfence();   // make g_dist[b] visible before signaling
    if (tid == 0)
        s_last = (atomicAdd(&g_counter, 1u) == (unsigned)(B_BATCH - 1));
    __syncthreads();

    if (s_last) {
        float s = 0.f;
        #pragma unroll
        for (int i = 0; i < B_BATCH / 256; i++)
            s += g_dist[tid + i * 256];

        #pragma unroll
        for (int off = 16; off > 0; off >>= 1)
            s += __shfl_xor_sync(0xFFFFFFFFu, s, off);
        if ((tid & 31) == 0) s_red[tid >> 5] = s;
        __syncthreads();
        if (tid < 8) {
            float w = s_red[tid];
            #pragma unroll
            for (int off = 4; off > 0; off >>= 1)
                w += __shfl_xor_sync(0xFFu, w, off);
            if (tid == 0) {
                out[0] = w * (1.0f / (float)B_BATCH);
                g_counter = 0;   // reset for next graph replay
            }
        }
    }
}

extern "C" void kernel_launch(void* const* d_in, const int* in_sizes, int n_in,
                              void* d_out, int out_size)
{
    const float* query   = (const float*)d_in[0];
    const float* support = (const float*)d_in[1];
    const int*   labels  = (const int*)d_in[2];
    float* out = (float*)d_out;

    proto_loss_kernel<<<B_BATCH, 256>>>(query, support, labels, out);
}

// round 6
// speedup vs baseline: 1.3256x; 1.0329x over previous
#include <cuda_runtime.h>
#include <cuda_bf16.h>

#define B_BATCH 8192
#define N_SUP   64
#define D_DIM   256
#define EPS     1e-8f

#define WARPS_PER_CTA 8
#define GRID_CTAS     (B_BATCH / WARPS_PER_CTA)   // 1024

__device__ float g_dist[B_BATCH];
__device__ unsigned int g_counter = 0;

// One WARP per batch row; warps fully autonomous (no smem / no barriers in
// the hot path). Lane owns dims [8*lane, 8*lane+8) as two float4.
__global__ __launch_bounds__(256) void proto_loss_kernel(
    const float* __restrict__ query,     // (B, D)
    const float* __restrict__ support,   // (B, N, D)
    const int*   __restrict__ labels,    // (B, N)
    float* __restrict__ out)             // scalar
{
    const int tid  = threadIdx.x;
    const int lane = tid & 31;
    const int wid  = tid >> 5;
    const int b    = blockIdx.x * WARPS_PER_CTA + wid;

    const float4* __restrict__ sup4 = reinterpret_cast<const float4*>(
        support + (size_t)b * N_SUP * D_DIM);

    // Label masks: 2 coalesced loads + 2 ballots per warp.
    const int lbase = b * N_SUP;
    const unsigned m0 = __ballot_sync(0xFFFFFFFFu, labels[lbase + lane] == 1);
    const unsigned m1 = __ballot_sync(0xFFFFFFFFu, labels[lbase + 32 + lane] == 1);
    const int cnt = __popc(m0) + __popc(m1);

    // Predicated accumulation over 64 support rows. Each enabled row:
    // warp reads 32 lanes * 32B = 1024B contiguous (2x LDG.128 per lane).
    // __ldcs: streaming (read-once) — keep L2 for query/labels.
    float4 a0 = make_float4(0.f, 0.f, 0.f, 0.f);
    float4 a1 = make_float4(0.f, 0.f, 0.f, 0.f);
    const int c0 = 2 * lane;

    #pragma unroll 4
    for (int n = 0; n < 32; n++) {
        if ((m0 >> n) & 1u) {
            float4 v0 = __ldcs(&sup4[n * (D_DIM / 4) + c0]);
            float4 v1 = __ldcs(&sup4[n * (D_DIM / 4) + c0 + 1]);
            a0.x += v0.x; a0.y += v0.y; a0.z += v0.z; a0.w += v0.w;
            a1.x += v1.x; a1.y += v1.y; a1.z += v1.z; a1.w += v1.w;
        }
    }
    #pragma unroll 4
    for (int n = 32; n < 64; n++) {
        if ((m1 >> (n - 32)) & 1u) {
            float4 v0 = __ldcs(&sup4[n * (D_DIM / 4) + c0]);
            float4 v1 = __ldcs(&sup4[n * (D_DIM / 4) + c0 + 1]);
            a0.x += v0.x; a0.y += v0.y; a0.z += v0.z; a0.w += v0.w;
            a1.x += v1.x; a1.y += v1.y; a1.z += v1.z; a1.w += v1.w;
        }
    }

    // Prototype (with count==0 fallback to support[b,0,:])
    float4 p0, p1;
    if (cnt > 0) {
        const float inv = 1.0f / (float)cnt;
        p0 = make_float4(a0.x * inv, a0.y * inv, a0.z * inv, a0.w * inv);
        p1 = make_float4(a1.x * inv, a1.y * inv, a1.z * inv, a1.w * inv);
    } else {
        p0 = sup4[c0];
        p1 = sup4[c0 + 1];
    }

    const float4* __restrict__ qry4 = reinterpret_cast<const float4*>(
        query + (size_t)b * D_DIM);
    const float4 q0 = qry4[c0];
    const float4 q1 = qry4[c0 + 1];

    float d;
    {
        float dx = q0.x - p0.x, dy = q0.y - p0.y, dz = q0.z - p0.z, dw = q0.w - p0.w;
        d = dx * dx + dy * dy + dz * dz + dw * dw;
        dx = q1.x - p1.x; dy = q1.y - p1.y; dz = q1.z - p1.z; dw = q1.w - p1.w;
        d += dx * dx + dy * dy + dz * dz + dw * dw;
    }
    #pragma unroll
    for (int off = 16; off > 0; off >>= 1)
        d += __shfl_xor_sync(0xFFFFFFFFu, d, off);

    if (lane == 0) g_dist[b] = sqrtf(d + EPS);

    // ---- last-CTA mean reduce (deterministic fixed-order sum) ----
    __threadfence();
    __syncthreads();
    __shared__ int s_last;
    __shared__ float s_red[WARPS_PER_CTA];
    if (tid == 0)
        s_last = (atomicAdd(&g_counter, 1u) == (unsigned)(GRID_CTAS - 1));
    __syncthreads();

    if (s_last) {
        float s = 0.f;
        #pragma unroll
        for (int i = 0; i < B_BATCH / 256; i++)
            s += g_dist[tid + i * 256];

        #pragma unroll
        for (int off = 16; off > 0; off >>= 1)
            s += __shfl_xor_sync(0xFFFFFFFFu, s, off);
        if (lane == 0) s_red[wid] = s;
        __syncthreads();
        if (tid < WARPS_PER_CTA) {
            float w = s_red[tid];
            #pragma unroll
            for (int off = WARPS_PER_CTA / 2; off > 0; off >>= 1)
                w += __shfl_xor_sync(0xFFu, w, off);
            if (tid == 0) {
                out[0] = w * (1.0f / (float)B_BATCH);
                g_counter = 0;   // reset for next graph replay
            }
        }
    }
}

extern "C" void kernel_launch(void* const* d_in, const int* in_sizes, int n_in,
                              void* d_out, int out_size)
{
    const float* query   = (const float*)d_in[0];
    const float* support = (const float*)d_in[1];
    const int*   labels  = (const int*)d_in[2];
    float* out = (float*)d_out;

    proto_loss_kernel<<<GRID_CTAS, 256>>>(query, support, labels, out);
}

// round 11
// speedup vs baseline: 1.5957x; 1.2037x over previous
#include <cuda_runtime.h>
#include <cuda_bf16.h>

#define B_BATCH 8192
#define N_SUP   64
#define D_DIM   256
#define EPS     1e-8f

#define WARPS_PER_CTA 8
#define GRID_CTAS     (B_BATCH / WARPS_PER_CTA)   // 1024

__device__ float g_dist[B_BATCH];
__device__ unsigned int g_counter = 0;

// One WARP per batch row. 64-reg budget (launch_bounds minBlocks=4) so ptxas
// can front-batch many predicated LDG.128s -> deep MLP per warp.
__global__ __launch_bounds__(256, 4) void proto_loss_kernel(
    const float* __restrict__ query,     // (B, D)
    const float* __restrict__ support,   // (B, N, D)
    const int*   __restrict__ labels,    // (B, N)
    float* __restrict__ out)             // scalar
{
    const int tid  = threadIdx.x;
    const int lane = tid & 31;
    const int wid  = tid >> 5;
    const int b    = blockIdx.x * WARPS_PER_CTA + wid;

    const float4* __restrict__ sup4 = reinterpret_cast<const float4*>(
        support + (size_t)b * N_SUP * D_DIM);

    // Label masks: 2 coalesced loads + 2 ballots per warp.
    const int lbase = b * N_SUP;
    const unsigned m0 = __ballot_sync(0xFFFFFFFFu, labels[lbase + lane] == 1);
    const unsigned m1 = __ballot_sync(0xFFFFFFFFu, labels[lbase + 32 + lane] == 1);
    const int cnt = __popc(m0) + __popc(m1);

    // Fully-unrolled dual-stream predicated accumulation.
    // Step n touches rows n (stream A, mask m0) and n+32 (stream B, mask m1):
    // 4 independent LDG.128 per step, immediate offsets, 4 accumulators.
    // Lane owns dims [8*lane, 8*lane+8) as two float4; an enabled row is a
    // 1KB fully-coalesced warp read. __ldcs: streaming, don't pollute L2.
    float4 a0 = make_float4(0.f, 0.f, 0.f, 0.f);
    float4 a1 = make_float4(0.f, 0.f, 0.f, 0.f);
    float4 b0 = make_float4(0.f, 0.f, 0.f, 0.f);
    float4 b1 = make_float4(0.f, 0.f, 0.f, 0.f);
    const int c0 = 2 * lane;

    #pragma unroll
    for (int n = 0; n < 32; n++) {
        if ((m0 >> n) & 1u) {
            float4 v0 = __ldcs(&sup4[n * (D_DIM / 4) + c0]);
            float4 v1 = __ldcs(&sup4[n * (D_DIM / 4) + c0 + 1]);
            a0.x += v0.x; a0.y += v0.y; a0.z += v0.z; a0.w += v0.w;
            a1.x += v1.x; a1.y += v1.y; a1.z += v1.z; a1.w += v1.w;
        }
        if ((m1 >> n) & 1u) {
            float4 w0 = __ldcs(&sup4[(n + 32) * (D_DIM / 4) + c0]);
            float4 w1 = __ldcs(&sup4[(n + 32) * (D_DIM / 4) + c0 + 1]);
            b0.x += w0.x; b0.y += w0.y; b0.z += w0.z; b0.w += w0.w;
            b1.x += w1.x; b1.y += w1.y; b1.z += w1.z; b1.w += w1.w;
        }
    }
    a0.x += b0.x; a0.y += b0.y; a0.z += b0.z; a0.w += b0.w;
    a1.x += b1.x; a1.y += b1.y; a1.z += b1.z; a1.w += b1.w;

    // Prototype (with count==0 fallback to support[b,0,:])
    float4 p0, p1;
    if (cnt > 0) {
        const float inv = 1.0f / (float)cnt;
        p0 = make_float4(a0.x * inv, a0.y * inv, a0.z * inv, a0.w * inv);
        p1 = make_float4(a1.x * inv, a1.y * inv, a1.z * inv, a1.w * inv);
    } else {
        p0 = sup4[c0];
        p1 = sup4[c0 + 1];
    }

    const float4* __restrict__ qry4 = reinterpret_cast<const float4*>(
        query + (size_t)b * D_DIM);
    const float4 q0 = qry4[c0];
    const float4 q1 = qry4[c0 + 1];

    float d;
    {
        float dx = q0.x - p0.x, dy = q0.y - p0.y, dz = q0.z - p0.z, dw = q0.w - p0.w;
        d = dx * dx + dy * dy + dz * dz + dw * dw;
        dx = q1.x - p1.x; dy = q1.y - p1.y; dz = q1.z - p1.z; dw = q1.w - p1.w;
        d += dx * dx + dy * dy + dz * dz + dw * dw;
    }
    #pragma unroll
    for (int off = 16; off > 0; off >>= 1)
        d += __shfl_xor_sync(0xFFFFFFFFu, d, off);

    if (lane == 0) g_dist[b] = sqrtf(d + EPS);

    // ---- last-CTA mean reduce (deterministic fixed-order sum) ----
    __threadfence();
    __syncthreads();
    __shared__ int s_last;
    __shared__ float s_red[WARPS_PER_CTA];
    if (tid == 0)
        s_last = (atomicAdd(&g_counter, 1u) == (unsigned)(GRID_CTAS - 1));
    __syncthreads();

    if (s_last) {
        float s = 0.f;
        #pragma unroll
        for (int i = 0; i < B_BATCH / 256; i++)
            s += g_dist[tid + i * 256];

        #pragma unroll
        for (int off = 16; off > 0; off >>= 1)
            s += __shfl_xor_sync(0xFFFFFFFFu, s, off);
        if (lane == 0) s_red[wid] = s;
        __syncthreads();
        if (tid < WARPS_PER_CTA) {
            float w = s_red[tid];
            #pragma unroll
            for (int off = WARPS_PER_CTA / 2; off > 0; off >>= 1)
                w += __shfl_xor_sync(0xFFu, w, off);
            if (tid == 0) {
                out[0] = w * (1.0f / (float)B_BATCH);
                g_counter = 0;   // reset for next graph replay
            }
        }
    }
}

extern "C" void kernel_launch(void* const* d_in, const int* in_sizes, int n_in,
                              void* d_out, int out_size)
{
    const float* query   = (const float*)d_in[0];
    const float* support = (const float*)d_in[1];
    const int*   labels  = (const int*)d_in[2];
    float* out = (float*)d_out;

    proto_loss_kernel<<<GRID_CTAS, 256>>>(query, support, labels, out);
}

// round 13
// speedup vs baseline: 1.7483x; 1.0957x over previous
#include <cuda_runtime.h>
#include <cuda_bf16.h>

#define B_BATCH 8192
#define N_SUP   64
#define D_DIM   256
#define EPS     1e-8f

#define WARPS_PER_CTA 8
#define ROWS_PER_WARP 2
#define GRID_CTAS     (B_BATCH / (WARPS_PER_CTA * ROWS_PER_WARP))   // 512

__device__ float g_dist[B_BATCH];
__device__ unsigned int g_counter = 0;

// One warp handles 2 batch rows sequentially. Grid = 512 CTAs -> all warps
// resident in one wave (SM capacity 4 CTAs @ 64 regs): no wave-quantization
// tail. Inner per-row code identical in structure to the R11 kernel.
__global__ __launch_bounds__(256, 4) void proto_loss_kernel(
    const float* __restrict__ query,     // (B, D)
    const float* __restrict__ support,   // (B, N, D)
    const int*   __restrict__ labels,    // (B, N)
    float* __restrict__ out)             // scalar
{
    const int tid  = threadIdx.x;
    const int lane = tid & 31;
    const int wid  = tid >> 5;
    const int gw   = blockIdx.x * WARPS_PER_CTA + wid;   // 0..4095
    const int c0   = 2 * lane;

    #pragma unroll 1
    for (int r = 0; r < ROWS_PER_WARP; r++) {
        const int b = ROWS_PER_WARP * gw + r;

        const float4* __restrict__ sup4 = reinterpret_cast<const float4*>(
            support + (size_t)b * N_SUP * D_DIM);

        // Label masks: 2 coalesced loads + 2 ballots.
        const int lbase = b * N_SUP;
        const unsigned m0 = __ballot_sync(0xFFFFFFFFu, labels[lbase + lane] == 1);
        const unsigned m1 = __ballot_sync(0xFFFFFFFFu, labels[lbase + 32 + lane] == 1);
        const int cnt = __popc(m0) + __popc(m1);

        // Fully-unrolled dual-stream predicated accumulation (4 independent
        // LDG.128 per step, immediate offsets, 4 accumulators). Lane owns
        // dims [8*lane, 8*lane+8); enabled row = 1KB coalesced warp read.
        float4 a0 = make_float4(0.f, 0.f, 0.f, 0.f);
        float4 a1 = make_float4(0.f, 0.f, 0.f, 0.f);
        float4 b0 = make_float4(0.f, 0.f, 0.f, 0.f);
        float4 b1 = make_float4(0.f, 0.f, 0.f, 0.f);

        #pragma unroll
        for (int n = 0; n < 32; n++) {
            if ((m0 >> n) & 1u) {
                float4 v0 = __ldcs(&sup4[n * (D_DIM / 4) + c0]);
                float4 v1 = __ldcs(&sup4[n * (D_DIM / 4) + c0 + 1]);
                a0.x += v0.x; a0.y += v0.y; a0.z += v0.z; a0.w += v0.w;
                a1.x += v1.x; a1.y += v1.y; a1.z += v1.z; a1.w += v1.w;
            }
            if ((m1 >> n) & 1u) {
                float4 w0 = __ldcs(&sup4[(n + 32) * (D_DIM / 4) + c0]);
                float4 w1 = __ldcs(&sup4[(n + 32) * (D_DIM / 4) + c0 + 1]);
                b0.x += w0.x; b0.y += w0.y; b0.z += w0.z; b0.w += w0.w;
                b1.x += w1.x; b1.y += w1.y; b1.z += w1.z; b1.w += w1.w;
            }
        }
        a0.x += b0.x; a0.y += b0.y; a0.z += b0.z; a0.w += b0.w;
        a1.x += b1.x; a1.y += b1.y; a1.z += b1.z; a1.w += b1.w;

        // Prototype (count==0 fallback to support[b,0,:])
        float4 p0, p1;
        if (cnt > 0) {
            const float inv = 1.0f / (float)cnt;
            p0 = make_float4(a0.x * inv, a0.y * inv, a0.z * inv, a0.w * inv);
            p1 = make_float4(a1.x * inv, a1.y * inv, a1.z * inv, a1.w * inv);
        } else {
            p0 = sup4[c0];
            p1 = sup4[c0 + 1];
        }

        const float4* __restrict__ qry4 = reinterpret_cast<const float4*>(
            query + (size_t)b * D_DIM);
        const float4 q0 = qry4[c0];
        const float4 q1 = qry4[c0 + 1];

        float d;
        {
            float dx = q0.x - p0.x, dy = q0.y - p0.y, dz = q0.z - p0.z, dw = q0.w - p0.w;
            d = dx * dx + dy * dy + dz * dz + dw * dw;
            dx = q1.x - p1.x; dy = q1.y - p1.y; dz = q1.z - p1.z; dw = q1.w - p1.w;
            d += dx * dx + dy * dy + dz * dz + dw * dw;
        }
        #pragma unroll
        for (int off = 16; off > 0; off >>= 1)
            d += __shfl_xor_sync(0xFFFFFFFFu, d, off);

        if (lane == 0) g_dist[b] = sqrtf(d + EPS);
    }

    // ---- last-CTA mean reduce (deterministic fixed-order sum) ----
    __threadfence();
    __syncthreads();
    __shared__ int s_last;
    __shared__ float s_red[WARPS_PER_CTA];
    if (tid == 0)
        s_last = (atomicAdd(&g_counter, 1u) == (unsigned)(GRID_CTAS - 1));
    __syncthreads();

    if (s_last) {
        float s = 0.f;
        #pragma unroll
        for (int i = 0; i < B_BATCH / 256; i++)
            s += g_dist[tid + i * 256];

        #pragma unroll
        for (int off = 16; off > 0; off >>= 1)
            s += __shfl_xor_sync(0xFFFFFFFFu, s, off);
        if (lane == 0) s_red[wid] = s;
        __syncthreads();
        if (tid < WARPS_PER_CTA) {
            float w = s_red[tid];
            #pragma unroll
            for (int off = WARPS_PER_CTA / 2; off > 0; off >>= 1)
                w += __shfl_xor_sync(0xFFu, w, off);
            if (tid == 0) {
                out[0] = w * (1.0f / (float)B_BATCH);
                g_counter = 0;   // reset for next graph replay
            }
        }
    }
}

extern "C" void kernel_launch(void* const* d_in, const int* in_sizes, int n_in,
                              void* d_out, int out_size)
{
    const float* query   = (const float*)d_in[0];
    const float* support = (const float*)d_in[1];
    const int*   labels  = (const int*)d_in[2];
    float* out = (float*)d_out;

    proto_loss_kernel<<<GRID_CTAS, 256>>>(query, support, labels, out);
}